// round 2
// baseline (speedup 1.0000x reference)
#include <cuda_runtime.h>
#include <math.h>

// WassersteinLog: per-batch 3x3 SPD matrix-sqrt pipeline.
//   A      = cov1 + eps*I
//   S      = sqrtm(A)                       (symmetric)
//   Sinv   = inv(S + eps*I)                 (symmetric)
//   C      = S * cov2 * S + eps*I           (symmetric)
//   Csq    = sqrtm(C)
//   X      = S * Csq * Sinv
//   covv   = X + X^T - 2*cov1
//   miuv   = miu2 - miu1
//
// sqrtm via eigenvalues only (trig cubic) + Newton divided differences of sqrt:
//   sqrt(A) = c0*I + c1*A + c2*A^2
//   d12 = 1/(s1+s2), d123 = -1/((s1+s2)(s2+s3)(s1+s3))   [always stable for SPD]
//   c2 = d123, c1 = d12 - d123*(l1+l2), c0 = s1 - d12*l1 + d123*l1*l2

namespace {

constexpr float EPSF = 1e-8f;

struct Sym3 { float m00, m01, m02, m11, m12, m22; };

__device__ __forceinline__ void eig3(const Sym3 A, float& l1, float& l2, float& l3) {
    const float third = 1.0f / 3.0f;
    float q  = (A.m00 + A.m11 + A.m22) * third;
    float p1 = A.m01 * A.m01 + A.m02 * A.m02 + A.m12 * A.m12;
    float b00 = A.m00 - q, b11 = A.m11 - q, b22 = A.m22 - q;
    float p2 = b00 * b00 + b11 * b11 + b22 * b22 + 2.0f * p1;
    if (p2 < 1e-28f) { l1 = l2 = l3 = q; return; }
    float p  = sqrtf(p2 * (1.0f / 6.0f));
    float ip = 1.0f / p;
    float c00 = b00 * ip, c11 = b11 * ip, c22 = b22 * ip;
    float c01 = A.m01 * ip, c02 = A.m02 * ip, c12 = A.m12 * ip;
    float detB = c00 * (c11 * c22 - c12 * c12)
               - c01 * (c01 * c22 - c12 * c02)
               + c02 * (c01 * c12 - c11 * c02);
    float r = 0.5f * detB;
    r = fminf(1.0f, fmaxf(-1.0f, r));
    float phi = acosf(r) * third;
    float tp  = 2.0f * p;
    l1 = q + tp * cosf(phi);
    l3 = q + tp * cosf(phi + 2.0943951023931953f);  // +2*pi/3
    l2 = 3.0f * q - l1 - l3;
}

// Matrix sqrt of SPD 3x3. If useFix: replace smallest eigenvalue with
// detFix/(l1*l2) when it is tiny relative to l1 (cancellation-free route).
// detS (product of sqrt-eigenvalues) optionally returned.
__device__ __forceinline__ Sym3 sqrtm3(const Sym3 A, bool useFix, float detFix, float* detS) {
    float l1, l2, l3;
    eig3(A, l1, l2, l3);
    if (useFix && l3 < 0.05f * l1) {
        float pl = l1 * l2;
        if (pl > 1e-30f) l3 = fmaxf(detFix / pl, 0.0f);
    }
    float s1 = sqrtf(fabsf(l1));
    float s2 = sqrtf(fabsf(l2));
    float s3 = sqrtf(fabsf(l3));
    if (detS) *detS = s1 * s2 * s3;
    const float g = 1e-20f;
    float d12 = 1.0f / (s1 + s2 + g);
    float d13 = 1.0f / (s1 + s3 + g);
    float d23 = 1.0f / (s2 + s3 + g);
    float c2 = -(d12 * d13 * d23);
    float c1 = d12 - c2 * (l1 + l2);
    float c0 = s1 - d12 * l1 + c2 * (l1 * l2);
    // A^2 (symmetric)
    float a00 = A.m00, a01 = A.m01, a02 = A.m02, a11 = A.m11, a12 = A.m12, a22 = A.m22;
    float q00 = a00 * a00 + a01 * a01 + a02 * a02;
    float q01 = a00 * a01 + a01 * a11 + a02 * a12;
    float q02 = a00 * a02 + a01 * a12 + a02 * a22;
    float q11 = a01 * a01 + a11 * a11 + a12 * a12;
    float q12 = a01 * a02 + a11 * a12 + a12 * a22;
    float q22 = a02 * a02 + a12 * a12 + a22 * a22;
    Sym3 S;
    S.m00 = c0 + c1 * a00 + c2 * q00;
    S.m01 =      c1 * a01 + c2 * q01;
    S.m02 =      c1 * a02 + c2 * q02;
    S.m11 = c0 + c1 * a11 + c2 * q11;
    S.m12 =      c1 * a12 + c2 * q12;
    S.m22 = c0 + c1 * a22 + c2 * q22;
    return S;
}

__global__ void __launch_bounds__(256)
wlog_kernel(const float* __restrict__ miu1,
            const float* __restrict__ miu2,
            const float* __restrict__ cov1,
            const float* __restrict__ cov2,
            float* __restrict__ out_miu,
            float* __restrict__ out_cov,
            int B) {
    int b = blockIdx.x * blockDim.x + threadIdx.x;
    if (b >= B) return;

    // ---- miu velocity ----
    const float* m1 = miu1 + 3 * (size_t)b;
    const float* m2 = miu2 + 3 * (size_t)b;
    float mo0 = m2[0] - m1[0];
    float mo1 = m2[1] - m1[1];
    float mo2 = m2[2] - m1[2];

    // ---- load covariances (exactly symmetric by construction) ----
    const float* v1 = cov1 + 9 * (size_t)b;
    const float* v2 = cov2 + 9 * (size_t)b;
    Sym3 V1, W;
    V1.m00 = v1[0]; V1.m01 = v1[1]; V1.m02 = v1[2];
    V1.m11 = v1[4]; V1.m12 = v1[5]; V1.m22 = v1[8];
    W.m00 = v2[0]; W.m01 = v2[1]; W.m02 = v2[2];
    W.m11 = v2[4]; W.m12 = v2[5]; W.m22 = v2[8];

    // ---- A = cov1 + eps*I ; S = sqrtm(A) ----
    Sym3 A = V1;
    A.m00 += EPSF; A.m11 += EPSF; A.m22 += EPSF;
    float detS;
    Sym3 S = sqrtm3(A, false, 0.0f, &detS);

    // ---- Sinv = inv(S + eps*I) (symmetric adjugate) ----
    float n00 = S.m00 + EPSF, n11 = S.m11 + EPSF, n22 = S.m22 + EPSF;
    float n01 = S.m01, n02 = S.m02, n12 = S.m12;
    float co00 = n11 * n22 - n12 * n12;
    float co01 = n02 * n12 - n01 * n22;
    float co02 = n01 * n12 - n02 * n11;
    float det  = n00 * co00 + n01 * co01 + n02 * co02;
    float idet = 1.0f / det;
    float i00 = co00 * idet;
    float i01 = co01 * idet;
    float i02 = co02 * idet;
    float i11 = (n00 * n22 - n02 * n02) * idet;
    float i12 = (n01 * n02 - n00 * n12) * idet;
    float i22 = (n00 * n11 - n01 * n01) * idet;

    // ---- C = S * W * S + eps*I ----
    // T = S * W (general 3x3)
    float T00 = S.m00 * W.m00 + S.m01 * W.m01 + S.m02 * W.m02;
    float T01 = S.m00 * W.m01 + S.m01 * W.m11 + S.m02 * W.m12;
    float T02 = S.m00 * W.m02 + S.m01 * W.m12 + S.m02 * W.m22;
    float T10 = S.m01 * W.m00 + S.m11 * W.m01 + S.m12 * W.m02;
    float T11 = S.m01 * W.m01 + S.m11 * W.m11 + S.m12 * W.m12;
    float T12 = S.m01 * W.m02 + S.m11 * W.m12 + S.m12 * W.m22;
    float T20 = S.m02 * W.m00 + S.m12 * W.m01 + S.m22 * W.m02;
    float T21 = S.m02 * W.m01 + S.m12 * W.m11 + S.m22 * W.m12;
    float T22 = S.m02 * W.m02 + S.m12 * W.m12 + S.m22 * W.m22;
    Sym3 C;
    C.m00 = T00 * S.m00 + T01 * S.m01 + T02 * S.m02 + EPSF;
    C.m01 = T00 * S.m01 + T01 * S.m11 + T02 * S.m12;
    C.m02 = T00 * S.m02 + T01 * S.m12 + T02 * S.m22;
    C.m11 = T10 * S.m01 + T11 * S.m11 + T12 * S.m12 + EPSF;
    C.m12 = T10 * S.m02 + T11 * S.m12 + T12 * S.m22;
    C.m22 = T20 * S.m02 + T21 * S.m12 + T22 * S.m22 + EPSF;

    // accurate det(C) = det(S)^2 * det(W)  (cancellation-free vs cofactor of C)
    float detW = W.m00 * (W.m11 * W.m22 - W.m12 * W.m12)
               - W.m01 * (W.m01 * W.m22 - W.m12 * W.m02)
               + W.m02 * (W.m01 * W.m12 - W.m11 * W.m02);
    float detC = detS * detS * detW;

    // ---- Csq = sqrtm(C) ----
    Sym3 Cs = sqrtm3(C, true, detC, nullptr);

    // ---- X = S * Csq * Sinv ----
    float U00 = S.m00 * Cs.m00 + S.m01 * Cs.m01 + S.m02 * Cs.m02;
    float U01 = S.m00 * Cs.m01 + S.m01 * Cs.m11 + S.m02 * Cs.m12;
    float U02 = S.m00 * Cs.m02 + S.m01 * Cs.m12 + S.m02 * Cs.m22;
    float U10 = S.m01 * Cs.m00 + S.m11 * Cs.m01 + S.m12 * Cs.m02;
    float U11 = S.m01 * Cs.m01 + S.m11 * Cs.m11 + S.m12 * Cs.m12;
    float U12 = S.m01 * Cs.m02 + S.m11 * Cs.m12 + S.m12 * Cs.m22;
    float U20 = S.m02 * Cs.m00 + S.m12 * Cs.m01 + S.m22 * Cs.m02;
    float U21 = S.m02 * Cs.m01 + S.m12 * Cs.m11 + S.m22 * Cs.m12;
    float U22 = S.m02 * Cs.m02 + S.m12 * Cs.m12 + S.m22 * Cs.m22;

    float X00 = U00 * i00 + U01 * i01 + U02 * i02;
    float X01 = U00 * i01 + U01 * i11 + U02 * i12;
    float X02 = U00 * i02 + U01 * i12 + U02 * i22;
    float X10 = U10 * i00 + U11 * i01 + U12 * i02;
    float X11 = U10 * i01 + U11 * i11 + U12 * i12;
    float X12 = U10 * i02 + U11 * i12 + U12 * i22;
    float X20 = U20 * i00 + U21 * i01 + U22 * i02;
    float X21 = U20 * i02 + U21 * i12 + U22 * i22;  // placeholder (recomputed below)
    // recompute X21 correctly: row2 * col1 of Sinv
    X21 = U20 * i01 + U21 * i11 + U22 * i12;
    float X22 = U20 * i02 + U21 * i12 + U22 * i22;

    // ---- cov velocity = X + X^T - 2*cov1 ----
    float O00 = 2.0f * (X00 - V1.m00);
    float O01 = X01 + X10 - 2.0f * V1.m01;
    float O02 = X02 + X20 - 2.0f * V1.m02;
    float O11 = 2.0f * (X11 - V1.m11);
    float O12 = X12 + X21 - 2.0f * V1.m12;
    float O22 = 2.0f * (X22 - V1.m22);

    // ---- stores ----
    float* om = out_miu + 3 * (size_t)b;
    om[0] = mo0; om[1] = mo1; om[2] = mo2;
    float* oc = out_cov + 9 * (size_t)b;
    oc[0] = O00; oc[1] = O01; oc[2] = O02;
    oc[3] = O01; oc[4] = O11; oc[5] = O12;
    oc[6] = O02; oc[7] = O12; oc[8] = O22;
}

}  // namespace

extern "C" void kernel_launch(void* const* d_in, const int* in_sizes, int n_in,
                              void* d_out, int out_size) {
    const float* miu1 = (const float*)d_in[0];
    const float* miu2 = (const float*)d_in[1];
    const float* cov1 = (const float*)d_in[2];
    const float* cov2 = (const float*)d_in[3];
    float* out = (float*)d_out;

    int B = in_sizes[0] / 3;
    float* out_miu = out;
    float* out_cov = out + (size_t)3 * B;

    int threads = 256;
    int blocks = (B + threads - 1) / threads;
    wlog_kernel<<<blocks, threads>>>(miu1, miu2, cov1, cov2, out_miu, out_cov, B);
}

// round 5
// speedup vs baseline: 1.3384x; 1.3384x over previous
#include <cuda_runtime.h>
#include <math.h>

// WassersteinLog: per-batch 3x3 SPD matrix-sqrt pipeline, smem-staged coalesced I/O.
//   A      = cov1 + eps*I
//   S      = sqrtm(A)                       (symmetric)
//   Sinv   = inv(S + eps*I)                 (symmetric)
//   C      = S * cov2 * S + eps*I           (symmetric)
//   Csq    = sqrtm(C)
//   X      = S * Csq * Sinv
//   covv   = X + X^T - 2*cov1
//   miuv   = miu2 - miu1
//
// sqrtm via eigenvalues only (trig cubic) + Newton divided differences of sqrt.

namespace {

constexpr float EPSF = 1e-8f;
constexpr int TPB = 256;
constexpr int CHUNK4 = (TPB * 9) / 4;   // 576 float4 per cov chunk

struct Sym3 { float m00, m01, m02, m11, m12, m22; };

__device__ __forceinline__ void eig3(const Sym3 A, float& l1, float& l2, float& l3) {
    const float third = 1.0f / 3.0f;
    float q  = (A.m00 + A.m11 + A.m22) * third;
    float p1 = A.m01 * A.m01 + A.m02 * A.m02 + A.m12 * A.m12;
    float b00 = A.m00 - q, b11 = A.m11 - q, b22 = A.m22 - q;
    float p2 = b00 * b00 + b11 * b11 + b22 * b22 + 2.0f * p1;
    if (p2 < 1e-28f) { l1 = l2 = l3 = q; return; }
    float p  = sqrtf(p2 * (1.0f / 6.0f));
    float ip = 1.0f / p;
    float c00 = b00 * ip, c11 = b11 * ip, c22 = b22 * ip;
    float c01 = A.m01 * ip, c02 = A.m02 * ip, c12 = A.m12 * ip;
    float detB = c00 * (c11 * c22 - c12 * c12)
               - c01 * (c01 * c22 - c12 * c02)
               + c02 * (c01 * c12 - c11 * c02);
    float r = 0.5f * detB;
    r = fminf(1.0f, fmaxf(-1.0f, r));
    float phi = acosf(r) * third;
    float tp  = 2.0f * p;
    l1 = q + tp * cosf(phi);
    l3 = q + tp * cosf(phi + 2.0943951023931953f);  // +2*pi/3
    l2 = 3.0f * q - l1 - l3;
}

__device__ __forceinline__ Sym3 sqrtm3(const Sym3 A, bool useFix, float detFix, float* detS) {
    float l1, l2, l3;
    eig3(A, l1, l2, l3);
    if (useFix && l3 < 0.05f * l1) {
        float pl = l1 * l2;
        if (pl > 1e-30f) l3 = fmaxf(detFix / pl, 0.0f);
    }
    float s1 = sqrtf(fabsf(l1));
    float s2 = sqrtf(fabsf(l2));
    float s3 = sqrtf(fabsf(l3));
    if (detS) *detS = s1 * s2 * s3;
    const float g = 1e-20f;
    float d12 = 1.0f / (s1 + s2 + g);
    float d13 = 1.0f / (s1 + s3 + g);
    float d23 = 1.0f / (s2 + s3 + g);
    float c2 = -(d12 * d13 * d23);
    float c1 = d12 - c2 * (l1 + l2);
    float c0 = s1 - d12 * l1 + c2 * (l1 * l2);
    float a00 = A.m00, a01 = A.m01, a02 = A.m02, a11 = A.m11, a12 = A.m12, a22 = A.m22;
    float q00 = a00 * a00 + a01 * a01 + a02 * a02;
    float q01 = a00 * a01 + a01 * a11 + a02 * a12;
    float q02 = a00 * a02 + a01 * a12 + a02 * a22;
    float q11 = a01 * a01 + a11 * a11 + a12 * a12;
    float q12 = a01 * a02 + a11 * a12 + a12 * a22;
    float q22 = a02 * a02 + a12 * a12 + a22 * a22;
    Sym3 S;
    S.m00 = c0 + c1 * a00 + c2 * q00;
    S.m01 =      c1 * a01 + c2 * q01;
    S.m02 =      c1 * a02 + c2 * q02;
    S.m11 = c0 + c1 * a11 + c2 * q11;
    S.m12 =      c1 * a12 + c2 * q12;
    S.m22 = c0 + c1 * a22 + c2 * q22;
    return S;
}

__global__ void __launch_bounds__(TPB)
wlog_kernel(const float* __restrict__ miu1,
            const float* __restrict__ miu2,
            const float* __restrict__ cov1,
            const float* __restrict__ cov2,
            float* __restrict__ out_miu,
            float* __restrict__ out_cov,
            int B) {
    __shared__ float s1[TPB * 9];
    __shared__ float s2[TPB * 9];

    const int base  = blockIdx.x * TPB;
    const int nElem = min(TPB, B - base);
    const int tid   = threadIdx.x;

    // ---- coalesced stage-in of cov chunks (thread-strided, bounded) ----
    if (nElem == TPB) {
        const float4* g1 = reinterpret_cast<const float4*>(cov1 + (size_t)base * 9);
        const float4* g2 = reinterpret_cast<const float4*>(cov2 + (size_t)base * 9);
        float4* a1 = reinterpret_cast<float4*>(s1);
        float4* a2 = reinterpret_cast<float4*>(s2);
        #pragma unroll
        for (int i = tid; i < CHUNK4; i += TPB) {
            a1[i] = g1[i];
            a2[i] = g2[i];
        }
    } else {
        for (int i = tid; i < nElem * 9; i += TPB) {
            s1[i] = cov1[(size_t)base * 9 + i];
            s2[i] = cov2[(size_t)base * 9 + i];
        }
    }
    __syncthreads();

    if (tid < nElem) {
        const float* v1 = s1 + 9 * tid;
        const float* v2 = s2 + 9 * tid;
        Sym3 V1, W;
        V1.m00 = v1[0]; V1.m01 = v1[1]; V1.m02 = v1[2];
        V1.m11 = v1[4]; V1.m12 = v1[5]; V1.m22 = v1[8];
        W.m00 = v2[0]; W.m01 = v2[1]; W.m02 = v2[2];
        W.m11 = v2[4]; W.m12 = v2[5]; W.m22 = v2[8];

        // ---- A = cov1 + eps*I ; S = sqrtm(A) ----
        Sym3 A = V1;
        A.m00 += EPSF; A.m11 += EPSF; A.m22 += EPSF;
        float detS;
        Sym3 S = sqrtm3(A, false, 0.0f, &detS);

        // ---- Sinv = inv(S + eps*I) ----
        float n00 = S.m00 + EPSF, n11 = S.m11 + EPSF, n22 = S.m22 + EPSF;
        float n01 = S.m01, n02 = S.m02, n12 = S.m12;
        float co00 = n11 * n22 - n12 * n12;
        float co01 = n02 * n12 - n01 * n22;
        float co02 = n01 * n12 - n02 * n11;
        float det  = n00 * co00 + n01 * co01 + n02 * co02;
        float idet = 1.0f / det;
        float i00 = co00 * idet;
        float i01 = co01 * idet;
        float i02 = co02 * idet;
        float i11 = (n00 * n22 - n02 * n02) * idet;
        float i12 = (n01 * n02 - n00 * n12) * idet;
        float i22 = (n00 * n11 - n01 * n01) * idet;

        // ---- C = S * W * S + eps*I ----
        float T00 = S.m00 * W.m00 + S.m01 * W.m01 + S.m02 * W.m02;
        float T01 = S.m00 * W.m01 + S.m01 * W.m11 + S.m02 * W.m12;
        float T02 = S.m00 * W.m02 + S.m01 * W.m12 + S.m02 * W.m22;
        float T10 = S.m01 * W.m00 + S.m11 * W.m01 + S.m12 * W.m02;
        float T11 = S.m01 * W.m01 + S.m11 * W.m11 + S.m12 * W.m12;
        float T12 = S.m01 * W.m02 + S.m11 * W.m12 + S.m12 * W.m22;
        float T20 = S.m02 * W.m00 + S.m12 * W.m01 + S.m22 * W.m02;
        float T21 = S.m02 * W.m01 + S.m12 * W.m11 + S.m22 * W.m12;
        float T22 = S.m02 * W.m02 + S.m12 * W.m12 + S.m22 * W.m22;
        Sym3 C;
        C.m00 = T00 * S.m00 + T01 * S.m01 + T02 * S.m02 + EPSF;
        C.m01 = T00 * S.m01 + T01 * S.m11 + T02 * S.m12;
        C.m02 = T00 * S.m02 + T01 * S.m12 + T02 * S.m22;
        C.m11 = T10 * S.m01 + T11 * S.m11 + T12 * S.m12 + EPSF;
        C.m12 = T10 * S.m02 + T11 * S.m12 + T12 * S.m22;
        C.m22 = T20 * S.m02 + T21 * S.m12 + T22 * S.m22 + EPSF;

        // cancellation-free det(C) = det(S)^2 * det(W)
        float detW = W.m00 * (W.m11 * W.m22 - W.m12 * W.m12)
                   - W.m01 * (W.m01 * W.m22 - W.m12 * W.m02)
                   + W.m02 * (W.m01 * W.m12 - W.m11 * W.m02);
        float detC = detS * detS * detW;

        // ---- Csq = sqrtm(C) ----
        Sym3 Cs = sqrtm3(C, true, detC, nullptr);

        // ---- X = S * Csq * Sinv ----
        float U00 = S.m00 * Cs.m00 + S.m01 * Cs.m01 + S.m02 * Cs.m02;
        float U01 = S.m00 * Cs.m01 + S.m01 * Cs.m11 + S.m02 * Cs.m12;
        float U02 = S.m00 * Cs.m02 + S.m01 * Cs.m12 + S.m02 * Cs.m22;
        float U10 = S.m01 * Cs.m00 + S.m11 * Cs.m01 + S.m12 * Cs.m02;
        float U11 = S.m01 * Cs.m01 + S.m11 * Cs.m11 + S.m12 * Cs.m12;
        float U12 = S.m01 * Cs.m02 + S.m11 * Cs.m12 + S.m12 * Cs.m22;
        float U20 = S.m02 * Cs.m00 + S.m12 * Cs.m01 + S.m22 * Cs.m02;
        float U21 = S.m02 * Cs.m01 + S.m12 * Cs.m11 + S.m22 * Cs.m12;
        float U22 = S.m02 * Cs.m02 + S.m12 * Cs.m12 + S.m22 * Cs.m22;

        float X00 = U00 * i00 + U01 * i01 + U02 * i02;
        float X01 = U00 * i01 + U01 * i11 + U02 * i12;
        float X02 = U00 * i02 + U01 * i12 + U02 * i22;
        float X10 = U10 * i00 + U11 * i01 + U12 * i02;
        float X11 = U10 * i01 + U11 * i11 + U12 * i12;
        float X12 = U10 * i02 + U11 * i12 + U12 * i22;
        float X20 = U20 * i00 + U21 * i01 + U22 * i02;
        float X21 = U20 * i01 + U21 * i11 + U22 * i12;
        float X22 = U20 * i02 + U21 * i12 + U22 * i22;

        // ---- cov velocity = X + X^T - 2*cov1, staged back into s1 ----
        float* oc = s1 + 9 * tid;   // thread-private slots: no sync hazard
        float O01 = X01 + X10 - 2.0f * V1.m01;
        float O02 = X02 + X20 - 2.0f * V1.m02;
        float O12 = X12 + X21 - 2.0f * V1.m12;
        oc[0] = 2.0f * (X00 - V1.m00);
        oc[1] = O01;
        oc[2] = O02;
        oc[3] = O01;
        oc[4] = 2.0f * (X11 - V1.m11);
        oc[5] = O12;
        oc[6] = O02;
        oc[7] = O12;
        oc[8] = 2.0f * (X22 - V1.m22);
    }
    __syncthreads();

    // ---- coalesced stage-out of cov chunk (thread-strided, bounded) ----
    if (nElem == TPB) {
        float4* go = reinterpret_cast<float4*>(out_cov + (size_t)base * 9);
        const float4* a1 = reinterpret_cast<const float4*>(s1);
        #pragma unroll
        for (int i = tid; i < CHUNK4; i += TPB) {
            go[i] = a1[i];
        }
    } else {
        for (int i = tid; i < nElem * 9; i += TPB) {
            out_cov[(size_t)base * 9 + i] = s1[i];
        }
    }

    // ---- miu velocity: flat float4 streaming ----
    const int nFlat = 3 * B;
    const int n4 = nFlat >> 2;
    int gtid = blockIdx.x * TPB + tid;
    const float4* m1_4 = reinterpret_cast<const float4*>(miu1);
    const float4* m2_4 = reinterpret_cast<const float4*>(miu2);
    float4* om_4 = reinterpret_cast<float4*>(out_miu);
    for (int j = gtid; j < n4; j += gridDim.x * TPB) {
        float4 a = m1_4[j];
        float4 c = m2_4[j];
        float4 o;
        o.x = c.x - a.x; o.y = c.y - a.y; o.z = c.z - a.z; o.w = c.w - a.w;
        om_4[j] = o;
    }
    // scalar tail (only if 3*B % 4 != 0)
    for (int j = (n4 << 2) + gtid; j < nFlat; j += gridDim.x * TPB) {
        out_miu[j] = miu2[j] - miu1[j];
    }
}

}  // namespace

extern "C" void kernel_launch(void* const* d_in, const int* in_sizes, int n_in,
                              void* d_out, int out_size) {
    const float* miu1 = (const float*)d_in[0];
    const float* miu2 = (const float*)d_in[1];
    const float* cov1 = (const float*)d_in[2];
    const float* cov2 = (const float*)d_in[3];
    float* out = (float*)d_out;

    int B = in_sizes[0] / 3;
    float* out_miu = out;
    float* out_cov = out + (size_t)3 * B;

    int blocks = (B + TPB - 1) / TPB;
    wlog_kernel<<<blocks, TPB>>>(miu1, miu2, cov1, cov2, out_miu, out_cov, B);
}

// round 6
// speedup vs baseline: 1.4514x; 1.0844x over previous
#include <cuda_runtime.h>
#include <math.h>

// WassersteinLog: per-batch 3x3 SPD matrix-sqrt pipeline, smem-staged coalesced I/O,
// fast-math transcendentals (precision budget: threshold 1e-3, we target <2e-4).
//   A      = cov1 + eps*I
//   S      = sqrtm(A)                       (symmetric)
//   Sinv   = inv(S + eps*I)                 (symmetric)
//   C      = S * cov2 * S + eps*I           (symmetric)
//   Csq    = sqrtm(C)
//   X      = S * Csq * Sinv
//   covv   = X + X^T - 2*cov1
//   miuv   = miu2 - miu1
//
// sqrtm via eigenvalues only (trig cubic) + Newton divided differences of sqrt.

namespace {

constexpr float EPSF = 1e-8f;
constexpr int TPB = 256;
constexpr int CHUNK4 = (TPB * 9) / 4;   // 576 float4 per cov chunk

__device__ __forceinline__ float fsqrt_fast(float x) {
    // MUFU.RSQ-based sqrt; exact 0 at x=0, valid for x >= 0.
    return x * rsqrtf(fmaxf(x, 1e-30f));
}

__device__ __forceinline__ float facos_fast(float r) {
    // Abramowitz-Stegun 4.4.45, abs err ~6.8e-5 rad, branchless sign handling.
    float ar = fabsf(r);
    float t  = fsqrt_fast(1.0f - ar);
    float p  = fmaf(fmaf(fmaf(-0.0187293f, ar, 0.0742610f), ar, -0.2121144f), ar, 1.5707288f);
    float a  = t * p;
    return (r >= 0.0f) ? a : (3.14159265358979f - a);
}

struct Sym3 { float m00, m01, m02, m11, m12, m22; };

__device__ __forceinline__ void eig3(const Sym3 A, float& l1, float& l2, float& l3) {
    const float third = 1.0f / 3.0f;
    float q  = (A.m00 + A.m11 + A.m22) * third;
    float p1 = A.m01 * A.m01 + A.m02 * A.m02 + A.m12 * A.m12;
    float b00 = A.m00 - q, b11 = A.m11 - q, b22 = A.m22 - q;
    float p2 = b00 * b00 + b11 * b11 + b22 * b22 + 2.0f * p1;
    if (p2 < 1e-28f) { l1 = l2 = l3 = q; return; }
    float p  = fsqrt_fast(p2 * (1.0f / 6.0f));
    float ip = __fdividef(1.0f, p);
    float c00 = b00 * ip, c11 = b11 * ip, c22 = b22 * ip;
    float c01 = A.m01 * ip, c02 = A.m02 * ip, c12 = A.m12 * ip;
    float detB = c00 * (c11 * c22 - c12 * c12)
               - c01 * (c01 * c22 - c12 * c02)
               + c02 * (c01 * c12 - c11 * c02);
    float r = 0.5f * detB;
    r = fminf(1.0f, fmaxf(-1.0f, r));
    float phi = facos_fast(r) * third;
    float tp  = 2.0f * p;
    l1 = q + tp * __cosf(phi);
    l3 = q + tp * __cosf(phi + 2.0943951023931953f);  // +2*pi/3
    l2 = 3.0f * q - l1 - l3;
}

__device__ __forceinline__ Sym3 sqrtm3(const Sym3 A, bool useFix, float detFix, float* detS) {
    float l1, l2, l3;
    eig3(A, l1, l2, l3);
    if (useFix && l3 < 0.05f * l1) {
        float pl = l1 * l2;
        if (pl > 1e-30f) l3 = fmaxf(__fdividef(detFix, pl), 0.0f);
    }
    float s1 = fsqrt_fast(fabsf(l1));
    float s2 = fsqrt_fast(fabsf(l2));
    float s3 = fsqrt_fast(fabsf(l3));
    if (detS) *detS = s1 * s2 * s3;
    const float g = 1e-20f;
    float d12 = __fdividef(1.0f, s1 + s2 + g);
    float d13 = __fdividef(1.0f, s1 + s3 + g);
    float d23 = __fdividef(1.0f, s2 + s3 + g);
    float c2 = -(d12 * d13 * d23);
    float c1 = d12 - c2 * (l1 + l2);
    float c0 = s1 - d12 * l1 + c2 * (l1 * l2);
    float a00 = A.m00, a01 = A.m01, a02 = A.m02, a11 = A.m11, a12 = A.m12, a22 = A.m22;
    float q00 = a00 * a00 + a01 * a01 + a02 * a02;
    float q01 = a00 * a01 + a01 * a11 + a02 * a12;
    float q02 = a00 * a02 + a01 * a12 + a02 * a22;
    float q11 = a01 * a01 + a11 * a11 + a12 * a12;
    float q12 = a01 * a02 + a11 * a12 + a12 * a22;
    float q22 = a02 * a02 + a12 * a12 + a22 * a22;
    Sym3 S;
    S.m00 = c0 + c1 * a00 + c2 * q00;
    S.m01 =      c1 * a01 + c2 * q01;
    S.m02 =      c1 * a02 + c2 * q02;
    S.m11 = c0 + c1 * a11 + c2 * q11;
    S.m12 =      c1 * a12 + c2 * q12;
    S.m22 = c0 + c1 * a22 + c2 * q22;
    return S;
}

__global__ void __launch_bounds__(TPB)
wlog_kernel(const float* __restrict__ miu1,
            const float* __restrict__ miu2,
            const float* __restrict__ cov1,
            const float* __restrict__ cov2,
            float* __restrict__ out_miu,
            float* __restrict__ out_cov,
            int B) {
    __shared__ float s1[TPB * 9];
    __shared__ float s2[TPB * 9];

    const int base  = blockIdx.x * TPB;
    const int nElem = min(TPB, B - base);
    const int tid   = threadIdx.x;

    // ---- coalesced stage-in of cov chunks (thread-strided, bounded) ----
    if (nElem == TPB) {
        const float4* g1 = reinterpret_cast<const float4*>(cov1 + (size_t)base * 9);
        const float4* g2 = reinterpret_cast<const float4*>(cov2 + (size_t)base * 9);
        float4* a1 = reinterpret_cast<float4*>(s1);
        float4* a2 = reinterpret_cast<float4*>(s2);
        #pragma unroll
        for (int i = tid; i < CHUNK4; i += TPB) {
            a1[i] = g1[i];
            a2[i] = g2[i];
        }
    } else {
        for (int i = tid; i < nElem * 9; i += TPB) {
            s1[i] = cov1[(size_t)base * 9 + i];
            s2[i] = cov2[(size_t)base * 9 + i];
        }
    }
    __syncthreads();

    if (tid < nElem) {
        const float* v1 = s1 + 9 * tid;
        const float* v2 = s2 + 9 * tid;
        Sym3 V1, W;
        V1.m00 = v1[0]; V1.m01 = v1[1]; V1.m02 = v1[2];
        V1.m11 = v1[4]; V1.m12 = v1[5]; V1.m22 = v1[8];
        W.m00 = v2[0]; W.m01 = v2[1]; W.m02 = v2[2];
        W.m11 = v2[4]; W.m12 = v2[5]; W.m22 = v2[8];

        // ---- A = cov1 + eps*I ; S = sqrtm(A) ----
        Sym3 A = V1;
        A.m00 += EPSF; A.m11 += EPSF; A.m22 += EPSF;
        float detS;
        Sym3 S = sqrtm3(A, false, 0.0f, &detS);

        // ---- Sinv = inv(S + eps*I) ----
        float n00 = S.m00 + EPSF, n11 = S.m11 + EPSF, n22 = S.m22 + EPSF;
        float n01 = S.m01, n02 = S.m02, n12 = S.m12;
        float co00 = n11 * n22 - n12 * n12;
        float co01 = n02 * n12 - n01 * n22;
        float co02 = n01 * n12 - n02 * n11;
        float det  = n00 * co00 + n01 * co01 + n02 * co02;
        float idet = __fdividef(1.0f, det);
        float i00 = co00 * idet;
        float i01 = co01 * idet;
        float i02 = co02 * idet;
        float i11 = (n00 * n22 - n02 * n02) * idet;
        float i12 = (n01 * n02 - n00 * n12) * idet;
        float i22 = (n00 * n11 - n01 * n01) * idet;

        // ---- C = S * W * S + eps*I ----
        float T00 = S.m00 * W.m00 + S.m01 * W.m01 + S.m02 * W.m02;
        float T01 = S.m00 * W.m01 + S.m01 * W.m11 + S.m02 * W.m12;
        float T02 = S.m00 * W.m02 + S.m01 * W.m12 + S.m02 * W.m22;
        float T10 = S.m01 * W.m00 + S.m11 * W.m01 + S.m12 * W.m02;
        float T11 = S.m01 * W.m01 + S.m11 * W.m11 + S.m12 * W.m12;
        float T12 = S.m01 * W.m02 + S.m11 * W.m12 + S.m12 * W.m22;
        float T20 = S.m02 * W.m00 + S.m12 * W.m01 + S.m22 * W.m02;
        float T21 = S.m02 * W.m01 + S.m12 * W.m11 + S.m22 * W.m12;
        float T22 = S.m02 * W.m02 + S.m12 * W.m12 + S.m22 * W.m22;
        Sym3 C;
        C.m00 = T00 * S.m00 + T01 * S.m01 + T02 * S.m02 + EPSF;
        C.m01 = T00 * S.m01 + T01 * S.m11 + T02 * S.m12;
        C.m02 = T00 * S.m02 + T01 * S.m12 + T02 * S.m22;
        C.m11 = T10 * S.m01 + T11 * S.m11 + T12 * S.m12 + EPSF;
        C.m12 = T10 * S.m02 + T11 * S.m12 + T12 * S.m22;
        C.m22 = T20 * S.m02 + T21 * S.m12 + T22 * S.m22 + EPSF;

        // cancellation-free det(C) = det(S)^2 * det(W)
        float detW = W.m00 * (W.m11 * W.m22 - W.m12 * W.m12)
                   - W.m01 * (W.m01 * W.m22 - W.m12 * W.m02)
                   + W.m02 * (W.m01 * W.m12 - W.m11 * W.m02);
        float detC = detS * detS * detW;

        // ---- Csq = sqrtm(C) ----
        Sym3 Cs = sqrtm3(C, true, detC, nullptr);

        // ---- X = S * Csq * Sinv ----
        float U00 = S.m00 * Cs.m00 + S.m01 * Cs.m01 + S.m02 * Cs.m02;
        float U01 = S.m00 * Cs.m01 + S.m01 * Cs.m11 + S.m02 * Cs.m12;
        float U02 = S.m00 * Cs.m02 + S.m01 * Cs.m12 + S.m02 * Cs.m22;
        float U10 = S.m01 * Cs.m00 + S.m11 * Cs.m01 + S.m12 * Cs.m02;
        float U11 = S.m01 * Cs.m01 + S.m11 * Cs.m11 + S.m12 * Cs.m12;
        float U12 = S.m01 * Cs.m02 + S.m11 * Cs.m12 + S.m12 * Cs.m22;
        float U20 = S.m02 * Cs.m00 + S.m12 * Cs.m01 + S.m22 * Cs.m02;
        float U21 = S.m02 * Cs.m01 + S.m12 * Cs.m11 + S.m22 * Cs.m12;
        float U22 = S.m02 * Cs.m02 + S.m12 * Cs.m12 + S.m22 * Cs.m22;

        float X00 = U00 * i00 + U01 * i01 + U02 * i02;
        float X01 = U00 * i01 + U01 * i11 + U02 * i12;
        float X02 = U00 * i02 + U01 * i12 + U02 * i22;
        float X10 = U10 * i00 + U11 * i01 + U12 * i02;
        float X11 = U10 * i01 + U11 * i11 + U12 * i12;
        float X12 = U10 * i02 + U11 * i12 + U12 * i22;
        float X20 = U20 * i00 + U21 * i01 + U22 * i02;
        float X21 = U20 * i01 + U21 * i11 + U22 * i12;
        float X22 = U20 * i02 + U21 * i12 + U22 * i22;

        // ---- cov velocity = X + X^T - 2*cov1, staged back into s1 ----
        float* oc = s1 + 9 * tid;   // thread-private slots: no sync hazard
        float O01 = X01 + X10 - 2.0f * V1.m01;
        float O02 = X02 + X20 - 2.0f * V1.m02;
        float O12 = X12 + X21 - 2.0f * V1.m12;
        oc[0] = 2.0f * (X00 - V1.m00);
        oc[1] = O01;
        oc[2] = O02;
        oc[3] = O01;
        oc[4] = 2.0f * (X11 - V1.m11);
        oc[5] = O12;
        oc[6] = O02;
        oc[7] = O12;
        oc[8] = 2.0f * (X22 - V1.m22);
    }
    __syncthreads();

    // ---- coalesced stage-out of cov chunk (thread-strided, bounded) ----
    if (nElem == TPB) {
        float4* go = reinterpret_cast<float4*>(out_cov + (size_t)base * 9);
        const float4* a1 = reinterpret_cast<const float4*>(s1);
        #pragma unroll
        for (int i = tid; i < CHUNK4; i += TPB) {
            go[i] = a1[i];
        }
    } else {
        for (int i = tid; i < nElem * 9; i += TPB) {
            out_cov[(size_t)base * 9 + i] = s1[i];
        }
    }

    // ---- miu velocity: flat float4 streaming ----
    const int nFlat = 3 * B;
    const int n4 = nFlat >> 2;
    int gtid = blockIdx.x * TPB + tid;
    const float4* m1_4 = reinterpret_cast<const float4*>(miu1);
    const float4* m2_4 = reinterpret_cast<const float4*>(miu2);
    float4* om_4 = reinterpret_cast<float4*>(out_miu);
    for (int j = gtid; j < n4; j += gridDim.x * TPB) {
        float4 a = m1_4[j];
        float4 c = m2_4[j];
        float4 o;
        o.x = c.x - a.x; o.y = c.y - a.y; o.z = c.z - a.z; o.w = c.w - a.w;
        om_4[j] = o;
    }
    // scalar tail (only if 3*B % 4 != 0)
    for (int j = (n4 << 2) + gtid; j < nFlat; j += gridDim.x * TPB) {
        out_miu[j] = miu2[j] - miu1[j];
    }
}

}  // namespace

extern "C" void kernel_launch(void* const* d_in, const int* in_sizes, int n_in,
                              void* d_out, int out_size) {
    const float* miu1 = (const float*)d_in[0];
    const float* miu2 = (const float*)d_in[1];
    const float* cov1 = (const float*)d_in[2];
    const float* cov2 = (const float*)d_in[3];
    float* out = (float*)d_out;

    int B = in_sizes[0] / 3;
    float* out_miu = out;
    float* out_cov = out + (size_t)3 * B;

    int blocks = (B + TPB - 1) / TPB;
    wlog_kernel<<<blocks, TPB>>>(miu1, miu2, cov1, cov2, out_miu, out_cov, B);
}

// round 8
// speedup vs baseline: 1.6514x; 1.1378x over previous
#include <cuda_runtime.h>
#include <math.h>

// WassersteinLog: per-batch 3x3 SPD matrix-sqrt pipeline, smem-staged coalesced I/O,
// fast-math transcendentals, occupancy-bounded (6 blocks/SM).
//   A      = cov1 + eps*I
//   S      = sqrtm(A)                       (symmetric)
//   Sinv   = inv(S + eps*I)                 (symmetric)
//   C      = S * cov2 * S + eps*I           (symmetric)
//   Csq    = sqrtm(C)
//   X      = S * Csq * Sinv
//   covv   = X + X^T - 2*cov1
//   miuv   = miu2 - miu1
//
// sqrtm via eigenvalues only (trig cubic) + Newton divided differences of sqrt.

namespace {

constexpr float EPSF = 1e-8f;
constexpr int TPB = 256;
constexpr int CHUNK4 = (TPB * 9) / 4;   // 576 float4 per cov chunk

__device__ __forceinline__ float fsqrt_fast(float x) {
    // MUFU.RSQ-based sqrt; exact 0 at x=0, valid for x >= 0.
    return x * rsqrtf(fmaxf(x, 1e-30f));
}

__device__ __forceinline__ float facos_fast(float r) {
    // Abramowitz-Stegun 4.4.45, abs err ~6.8e-5 rad, branchless sign handling.
    float ar = fabsf(r);
    float t  = fsqrt_fast(1.0f - ar);
    float p  = fmaf(fmaf(fmaf(-0.0187293f, ar, 0.0742610f), ar, -0.2121144f), ar, 1.5707288f);
    float a  = t * p;
    return (r >= 0.0f) ? a : (3.14159265358979f - a);
}

struct Sym3 { float m00, m01, m02, m11, m12, m22; };

__device__ __forceinline__ void eig3(const Sym3 A, float& l1, float& l2, float& l3) {
    const float third = 1.0f / 3.0f;
    float q  = (A.m00 + A.m11 + A.m22) * third;
    float p1 = A.m01 * A.m01 + A.m02 * A.m02 + A.m12 * A.m12;
    float b00 = A.m00 - q, b11 = A.m11 - q, b22 = A.m22 - q;
    float p2 = b00 * b00 + b11 * b11 + b22 * b22 + 2.0f * p1;
    if (p2 < 1e-24f) { l1 = l2 = l3 = q; return; }   // isotropic to ~1e-12
    float t   = p2 * (1.0f / 6.0f);
    float irt = rsqrtf(t);        // 1/p
    float p   = t * irt;          // p = sqrt(t)
    // raw det(B) without normalization; r = det(B) / (2 p^3), progressive scaling
    float detB = b00 * (b11 * b22 - A.m12 * A.m12)
               - A.m01 * (A.m01 * b22 - A.m12 * A.m02)
               + A.m02 * (A.m01 * A.m12 - b11 * A.m02);
    float r = 0.5f * (((detB * irt) * irt) * irt);
    r = fminf(1.0f, fmaxf(-1.0f, r));
    float phi = facos_fast(r) * third;
    float tp  = 2.0f * p;
    l1 = q + tp * __cosf(phi);
    l3 = q + tp * __cosf(phi + 2.0943951023931953f);  // +2*pi/3
    l2 = 3.0f * q - l1 - l3;
}

__device__ __forceinline__ Sym3 sqrtm3(const Sym3 A, bool useFix, float detFix, float* detS) {
    float l1, l2, l3;
    eig3(A, l1, l2, l3);
    if (useFix && l3 < 0.05f * l1) {
        float pl = l1 * l2;
        if (pl > 1e-30f) l3 = fmaxf(__fdividef(detFix, pl), 0.0f);
    }
    float s1 = fsqrt_fast(fabsf(l1));
    float s2 = fsqrt_fast(fabsf(l2));
    float s3 = fsqrt_fast(fabsf(l3));
    if (detS) *detS = s1 * s2 * s3;
    const float g = 1e-20f;
    float d12 = __fdividef(1.0f, s1 + s2 + g);
    float d13 = __fdividef(1.0f, s1 + s3 + g);
    float d23 = __fdividef(1.0f, s2 + s3 + g);
    float c2 = -(d12 * d13 * d23);
    float c1 = d12 - c2 * (l1 + l2);
    float c0 = s1 - d12 * l1 + c2 * (l1 * l2);
    float a00 = A.m00, a01 = A.m01, a02 = A.m02, a11 = A.m11, a12 = A.m12, a22 = A.m22;
    float q00 = a00 * a00 + a01 * a01 + a02 * a02;
    float q01 = a00 * a01 + a01 * a11 + a02 * a12;
    float q02 = a00 * a02 + a01 * a12 + a02 * a22;
    float q11 = a01 * a01 + a11 * a11 + a12 * a12;
    float q12 = a01 * a02 + a11 * a12 + a12 * a22;
    float q22 = a02 * a02 + a12 * a12 + a22 * a22;
    Sym3 S;
    S.m00 = c0 + c1 * a00 + c2 * q00;
    S.m01 =      c1 * a01 + c2 * q01;
    S.m02 =      c1 * a02 + c2 * q02;
    S.m11 = c0 + c1 * a11 + c2 * q11;
    S.m12 =      c1 * a12 + c2 * q12;
    S.m22 = c0 + c1 * a22 + c2 * q22;
    return S;
}

__global__ void __launch_bounds__(TPB, 6)
wlog_kernel(const float* __restrict__ miu1,
            const float* __restrict__ miu2,
            const float* __restrict__ cov1,
            const float* __restrict__ cov2,
            float* __restrict__ out_miu,
            float* __restrict__ out_cov,
            int B) {
    __shared__ float s1[TPB * 9];
    __shared__ float s2[TPB * 9];

    const int base  = blockIdx.x * TPB;
    const int nElem = min(TPB, B - base);
    const int tid   = threadIdx.x;

    // ---- coalesced stage-in of cov chunks (thread-strided, bounded) ----
    if (nElem == TPB) {
        const float4* g1 = reinterpret_cast<const float4*>(cov1 + (size_t)base * 9);
        const float4* g2 = reinterpret_cast<const float4*>(cov2 + (size_t)base * 9);
        float4* a1 = reinterpret_cast<float4*>(s1);
        float4* a2 = reinterpret_cast<float4*>(s2);
        #pragma unroll
        for (int i = tid; i < CHUNK4; i += TPB) {
            a1[i] = g1[i];
            a2[i] = g2[i];
        }
    } else {
        for (int i = tid; i < nElem * 9; i += TPB) {
            s1[i] = cov1[(size_t)base * 9 + i];
            s2[i] = cov2[(size_t)base * 9 + i];
        }
    }
    __syncthreads();

    if (tid < nElem) {
        const float* v1 = s1 + 9 * tid;
        const float* v2 = s2 + 9 * tid;
        Sym3 V1, W;
        V1.m00 = v1[0]; V1.m01 = v1[1]; V1.m02 = v1[2];
        V1.m11 = v1[4]; V1.m12 = v1[5]; V1.m22 = v1[8];
        W.m00 = v2[0]; W.m01 = v2[1]; W.m02 = v2[2];
        W.m11 = v2[4]; W.m12 = v2[5]; W.m22 = v2[8];

        // ---- A = cov1 + eps*I ; S = sqrtm(A) ----
        Sym3 A = V1;
        A.m00 += EPSF; A.m11 += EPSF; A.m22 += EPSF;
        float detS;
        Sym3 S = sqrtm3(A, false, 0.0f, &detS);

        // ---- Sinv = inv(S + eps*I) ----
        float n00 = S.m00 + EPSF, n11 = S.m11 + EPSF, n22 = S.m22 + EPSF;
        float n01 = S.m01, n02 = S.m02, n12 = S.m12;
        float co00 = n11 * n22 - n12 * n12;
        float co01 = n02 * n12 - n01 * n22;
        float co02 = n01 * n12 - n02 * n11;
        float det  = n00 * co00 + n01 * co01 + n02 * co02;
        float idet = __fdividef(1.0f, det);
        float i00 = co00 * idet;
        float i01 = co01 * idet;
        float i02 = co02 * idet;
        float i11 = (n00 * n22 - n02 * n02) * idet;
        float i12 = (n01 * n02 - n00 * n12) * idet;
        float i22 = (n00 * n11 - n01 * n01) * idet;

        // ---- C = S * W * S + eps*I ----
        float T00 = S.m00 * W.m00 + S.m01 * W.m01 + S.m02 * W.m02;
        float T01 = S.m00 * W.m01 + S.m01 * W.m11 + S.m02 * W.m12;
        float T02 = S.m00 * W.m02 + S.m01 * W.m12 + S.m02 * W.m22;
        float T10 = S.m01 * W.m00 + S.m11 * W.m01 + S.m12 * W.m02;
        float T11 = S.m01 * W.m01 + S.m11 * W.m11 + S.m12 * W.m12;
        float T12 = S.m01 * W.m02 + S.m11 * W.m12 + S.m12 * W.m22;
        float T20 = S.m02 * W.m00 + S.m12 * W.m01 + S.m22 * W.m02;
        float T21 = S.m02 * W.m01 + S.m12 * W.m11 + S.m22 * W.m12;
        float T22 = S.m02 * W.m02 + S.m12 * W.m12 + S.m22 * W.m22;
        Sym3 C;
        C.m00 = T00 * S.m00 + T01 * S.m01 + T02 * S.m02 + EPSF;
        C.m01 = T00 * S.m01 + T01 * S.m11 + T02 * S.m12;
        C.m02 = T00 * S.m02 + T01 * S.m12 + T02 * S.m22;
        C.m11 = T10 * S.m01 + T11 * S.m11 + T12 * S.m12 + EPSF;
        C.m12 = T10 * S.m02 + T11 * S.m12 + T12 * S.m22;
        C.m22 = T20 * S.m02 + T21 * S.m12 + T22 * S.m22 + EPSF;

        // cancellation-free det(C) = det(S)^2 * det(W)
        float detW = W.m00 * (W.m11 * W.m22 - W.m12 * W.m12)
                   - W.m01 * (W.m01 * W.m22 - W.m12 * W.m02)
                   + W.m02 * (W.m01 * W.m12 - W.m11 * W.m02);
        float detC = detS * detS * detW;

        // ---- Csq = sqrtm(C) ----
        Sym3 Cs = sqrtm3(C, true, detC, nullptr);

        // ---- X = S * Csq * Sinv ----
        float U00 = S.m00 * Cs.m00 + S.m01 * Cs.m01 + S.m02 * Cs.m02;
        float U01 = S.m00 * Cs.m01 + S.m01 * Cs.m11 + S.m02 * Cs.m12;
        float U02 = S.m00 * Cs.m02 + S.m01 * Cs.m12 + S.m02 * Cs.m22;
        float U10 = S.m01 * Cs.m00 + S.m11 * Cs.m01 + S.m12 * Cs.m02;
        float U11 = S.m01 * Cs.m01 + S.m11 * Cs.m11 + S.m12 * Cs.m12;
        float U12 = S.m01 * Cs.m02 + S.m11 * Cs.m12 + S.m12 * Cs.m22;
        float U20 = S.m02 * Cs.m00 + S.m12 * Cs.m01 + S.m22 * Cs.m02;
        float U21 = S.m02 * Cs.m01 + S.m12 * Cs.m11 + S.m22 * Cs.m12;
        float U22 = S.m02 * Cs.m02 + S.m12 * Cs.m12 + S.m22 * Cs.m22;

        float X00 = U00 * i00 + U01 * i01 + U02 * i02;
        float X01 = U00 * i01 + U01 * i11 + U02 * i12;
        float X02 = U00 * i02 + U01 * i12 + U02 * i22;
        float X10 = U10 * i00 + U11 * i01 + U12 * i02;
        float X11 = U10 * i01 + U11 * i11 + U12 * i12;
        float X12 = U10 * i02 + U11 * i12 + U12 * i22;
        float X20 = U20 * i00 + U21 * i01 + U22 * i02;
        float X21 = U20 * i01 + U21 * i11 + U22 * i12;
        float X22 = U20 * i02 + U21 * i12 + U22 * i22;

        // ---- cov velocity = X + X^T - 2*cov1, staged back into s1 ----
        float* oc = s1 + 9 * tid;   // thread-private slots: no sync hazard
        float O01 = X01 + X10 - 2.0f * V1.m01;
        float O02 = X02 + X20 - 2.0f * V1.m02;
        float O12 = X12 + X21 - 2.0f * V1.m12;
        oc[0] = 2.0f * (X00 - V1.m00);
        oc[1] = O01;
        oc[2] = O02;
        oc[3] = O01;
        oc[4] = 2.0f * (X11 - V1.m11);
        oc[5] = O12;
        oc[6] = O02;
        oc[7] = O12;
        oc[8] = 2.0f * (X22 - V1.m22);
    }
    __syncthreads();

    // ---- coalesced stage-out of cov chunk (thread-strided, bounded) ----
    if (nElem == TPB) {
        float4* go = reinterpret_cast<float4*>(out_cov + (size_t)base * 9);
        const float4* a1 = reinterpret_cast<const float4*>(s1);
        #pragma unroll
        for (int i = tid; i < CHUNK4; i += TPB) {
            go[i] = a1[i];
        }
    } else {
        for (int i = tid; i < nElem * 9; i += TPB) {
            out_cov[(size_t)base * 9 + i] = s1[i];
        }
    }

    // ---- miu velocity: flat float4 streaming ----
    const int nFlat = 3 * B;
    const int n4 = nFlat >> 2;
    int gtid = blockIdx.x * TPB + tid;
    const float4* m1_4 = reinterpret_cast<const float4*>(miu1);
    const float4* m2_4 = reinterpret_cast<const float4*>(miu2);
    float4* om_4 = reinterpret_cast<float4*>(out_miu);
    for (int j = gtid; j < n4; j += gridDim.x * TPB) {
        float4 a = m1_4[j];
        float4 c = m2_4[j];
        float4 o;
        o.x = c.x - a.x; o.y = c.y - a.y; o.z = c.z - a.z; o.w = c.w - a.w;
        om_4[j] = o;
    }
    // scalar tail (only if 3*B % 4 != 0)
    for (int j = (n4 << 2) + gtid; j < nFlat; j += gridDim.x * TPB) {
        out_miu[j] = miu2[j] - miu1[j];
    }
}

}  // namespace

extern "C" void kernel_launch(void* const* d_in, const int* in_sizes, int n_in,
                              void* d_out, int out_size) {
    const float* miu1 = (const float*)d_in[0];
    const float* miu2 = (const float*)d_in[1];
    const float* cov1 = (const float*)d_in[2];
    const float* cov2 = (const float*)d_in[3];
    float* out = (float*)d_out;

    int B = in_sizes[0] / 3;
    float* out_miu = out;
    float* out_cov = out + (size_t)3 * B;

    int blocks = (B + TPB - 1) / TPB;
    wlog_kernel<<<blocks, TPB>>>(miu1, miu2, cov1, cov2, out_miu, out_cov, B);
}

// round 9
// speedup vs baseline: 1.7696x; 1.0716x over previous
#include <cuda_runtime.h>
#include <math.h>

// WassersteinLog via the similarity identity:
//   X = S sqrt(S W S + eps I) inv(S) = sqrt(A W + eps I),  A = cov1 + eps I, W = cov2
//   covv = X + X^T - 2 cov1 ;  miuv = miu2 - miu1
// sqrt of the (diagonalizable, real-positive-spectrum) 3x3 M = A W via
// eigenvalues (trig cubic on char poly) + Newton divided differences:
//   sqrt(M) = c0 I + c1 M + c2 M^2
// det(M) = det(A) det(W) is cancellation-free and patches the smallest eigenvalue.

namespace {

constexpr float EPSF = 1e-8f;
constexpr int TPB = 256;
constexpr int CHUNK4 = (TPB * 9) / 4;   // 576 float4 per cov chunk

__device__ __forceinline__ float fsqrt_fast(float x) {
    return x * rsqrtf(fmaxf(x, 1e-30f));
}

__device__ __forceinline__ float facos_fast(float r) {
    // Abramowitz-Stegun 4.4.45, abs err ~6.8e-5 rad, branchless sign handling.
    float ar = fabsf(r);
    float t  = fsqrt_fast(1.0f - ar);
    float p  = fmaf(fmaf(fmaf(-0.0187293f, ar, 0.0742610f), ar, -0.2121144f), ar, 1.5707288f);
    float a  = t * p;
    return (r >= 0.0f) ? a : (3.14159265358979f - a);
}

__global__ void __launch_bounds__(TPB, 8)
wlog_kernel(const float* __restrict__ miu1,
            const float* __restrict__ miu2,
            const float* __restrict__ cov1,
            const float* __restrict__ cov2,
            float* __restrict__ out_miu,
            float* __restrict__ out_cov,
            int B) {
    __shared__ float s1[TPB * 9];
    __shared__ float s2[TPB * 9];

    const int base  = blockIdx.x * TPB;
    const int nElem = min(TPB, B - base);
    const int tid   = threadIdx.x;

    // ---- coalesced stage-in of cov chunks ----
    if (nElem == TPB) {
        const float4* g1 = reinterpret_cast<const float4*>(cov1 + (size_t)base * 9);
        const float4* g2 = reinterpret_cast<const float4*>(cov2 + (size_t)base * 9);
        float4* a1 = reinterpret_cast<float4*>(s1);
        float4* a2 = reinterpret_cast<float4*>(s2);
        #pragma unroll
        for (int i = tid; i < CHUNK4; i += TPB) {
            a1[i] = g1[i];
            a2[i] = g2[i];
        }
    } else {
        for (int i = tid; i < nElem * 9; i += TPB) {
            s1[i] = cov1[(size_t)base * 9 + i];
            s2[i] = cov2[(size_t)base * 9 + i];
        }
    }
    __syncthreads();

    if (tid < nElem) {
        const float* v1 = s1 + 9 * tid;
        const float* v2 = s2 + 9 * tid;
        // A = cov1 + eps I (symmetric), W = cov2 (symmetric)
        float A00 = v1[0] + EPSF, A01 = v1[1], A02 = v1[2];
        float A11 = v1[4] + EPSF, A12 = v1[5], A22 = v1[8];
        float W00 = v2[0], W01 = v2[1], W02 = v2[2];
        float W11 = v2[4], W12 = v2[5], W22 = v2[8];

        // ---- M = A * W + eps I  (general 3x3) ----
        float M00 = A00 * W00 + A01 * W01 + A02 * W02 + EPSF;
        float M01 = A00 * W01 + A01 * W11 + A02 * W12;
        float M02 = A00 * W02 + A01 * W12 + A02 * W22;
        float M10 = A01 * W00 + A11 * W01 + A12 * W02;
        float M11 = A01 * W01 + A11 * W11 + A12 * W12 + EPSF;
        float M12 = A01 * W02 + A11 * W12 + A12 * W22;
        float M20 = A02 * W00 + A12 * W01 + A22 * W02;
        float M21 = A02 * W01 + A12 * W11 + A22 * W12;
        float M22 = A02 * W02 + A12 * W12 + A22 * W22 + EPSF;

        // ---- cancellation-free det(M) = det(A) * det(W) ----
        float detA = A00 * (A11 * A22 - A12 * A12)
                   - A01 * (A01 * A22 - A12 * A02)
                   + A02 * (A01 * A12 - A11 * A02);
        float detW = W00 * (W11 * W22 - W12 * W12)
                   - W01 * (W01 * W22 - W12 * W02)
                   + W02 * (W01 * W12 - W11 * W02);
        float detM = detA * detW;

        // ---- eigenvalues of M (real, positive) via trig cubic ----
        const float third = 1.0f / 3.0f;
        float q = (M00 + M11 + M22) * third;
        float B00 = M00 - q, B11 = M11 - q, B22 = M22 - q;
        float p2 = B00 * B00 + B11 * B11 + B22 * B22
                 + 2.0f * (M01 * M10 + M02 * M20 + M12 * M21);
        p2 = fmaxf(p2, 0.0f);
        float l1, l2, l3;
        if (p2 < 1e-24f) {
            l1 = l2 = l3 = q;
        } else {
            float t   = p2 * (1.0f / 6.0f);
            float irt = rsqrtf(t);      // 1/p
            float p   = t * irt;        // p
            float detB = B00 * (B11 * B22 - M12 * M21)
                       - M01 * (M10 * B22 - M12 * M20)
                       + M02 * (M10 * M21 - B11 * M20);
            float r = 0.5f * (((detB * irt) * irt) * irt);
            r = fminf(1.0f, fmaxf(-1.0f, r));
            float phi = facos_fast(r) * third;
            float tp  = 2.0f * p;
            l1 = q + tp * __cosf(phi);
            l3 = q + tp * __cosf(phi + 2.0943951023931953f);  // +2*pi/3
            l2 = 3.0f * q - l1 - l3;
        }
        // patch smallest eigenvalue from the accurate determinant
        if (l3 < 0.05f * l1) {
            float pl = l1 * l2;
            if (pl > 1e-30f) l3 = fmaxf(__fdividef(detM, pl), 0.0f);
        }

        // ---- divided-difference coefficients of sqrt ----
        float sq1 = fsqrt_fast(fabsf(l1));
        float sq2 = fsqrt_fast(fabsf(l2));
        float sq3 = fsqrt_fast(fabsf(l3));
        const float g = 1e-20f;
        float d12 = __fdividef(1.0f, sq1 + sq2 + g);
        float d13 = __fdividef(1.0f, sq1 + sq3 + g);
        float d23 = __fdividef(1.0f, sq2 + sq3 + g);
        float c2 = -(d12 * d13 * d23);
        float c1 = d12 - c2 * (l1 + l2);
        float c0 = sq1 - d12 * l1 + c2 * (l1 * l2);

        // ---- M^2 (all 9 entries) ----
        float P00 = M00 * M00 + M01 * M10 + M02 * M20;
        float P01 = M00 * M01 + M01 * M11 + M02 * M21;
        float P02 = M00 * M02 + M01 * M12 + M02 * M22;
        float P10 = M10 * M00 + M11 * M10 + M12 * M20;
        float P11 = M10 * M01 + M11 * M11 + M12 * M21;
        float P12 = M10 * M02 + M11 * M12 + M12 * M22;
        float P20 = M20 * M00 + M21 * M10 + M22 * M20;
        float P21 = M20 * M01 + M21 * M11 + M22 * M21;
        float P22 = M20 * M02 + M21 * M12 + M22 * M22;

        // ---- covv = X + X^T - 2 cov1, X = c0 I + c1 M + c2 M^2 ----
        float O00 = 2.0f * (c0 + c1 * M00 + c2 * P00 - v1[0]);
        float O11 = 2.0f * (c0 + c1 * M11 + c2 * P11 - v1[4]);
        float O22 = 2.0f * (c0 + c1 * M22 + c2 * P22 - v1[8]);
        float O01 = c1 * (M01 + M10) + c2 * (P01 + P10) - 2.0f * v1[1];
        float O02 = c1 * (M02 + M20) + c2 * (P02 + P20) - 2.0f * v1[2];
        float O12 = c1 * (M12 + M21) + c2 * (P12 + P21) - 2.0f * v1[5];

        // stage back into s1 (thread-private slots)
        float* oc = s1 + 9 * tid;
        oc[0] = O00; oc[1] = O01; oc[2] = O02;
        oc[3] = O01; oc[4] = O11; oc[5] = O12;
        oc[6] = O02; oc[7] = O12; oc[8] = O22;
    }
    __syncthreads();

    // ---- coalesced stage-out of cov chunk ----
    if (nElem == TPB) {
        float4* go = reinterpret_cast<float4*>(out_cov + (size_t)base * 9);
        const float4* a1 = reinterpret_cast<const float4*>(s1);
        #pragma unroll
        for (int i = tid; i < CHUNK4; i += TPB) {
            go[i] = a1[i];
        }
    } else {
        for (int i = tid; i < nElem * 9; i += TPB) {
            out_cov[(size_t)base * 9 + i] = s1[i];
        }
    }

    // ---- miu velocity: flat float4 streaming ----
    const int nFlat = 3 * B;
    const int n4 = nFlat >> 2;
    int gtid = blockIdx.x * TPB + tid;
    const float4* m1_4 = reinterpret_cast<const float4*>(miu1);
    const float4* m2_4 = reinterpret_cast<const float4*>(miu2);
    float4* om_4 = reinterpret_cast<float4*>(out_miu);
    for (int j = gtid; j < n4; j += gridDim.x * TPB) {
        float4 a = m1_4[j];
        float4 c = m2_4[j];
        float4 o;
        o.x = c.x - a.x; o.y = c.y - a.y; o.z = c.z - a.z; o.w = c.w - a.w;
        om_4[j] = o;
    }
    for (int j = (n4 << 2) + gtid; j < nFlat; j += gridDim.x * TPB) {
        out_miu[j] = miu2[j] - miu1[j];
    }
}

}  // namespace

extern "C" void kernel_launch(void* const* d_in, const int* in_sizes, int n_in,
                              void* d_out, int out_size) {
    const float* miu1 = (const float*)d_in[0];
    const float* miu2 = (const float*)d_in[1];
    const float* cov1 = (const float*)d_in[2];
    const float* cov2 = (const float*)d_in[3];
    float* out = (float*)d_out;

    int B = in_sizes[0] / 3;
    float* out_miu = out;
    float* out_cov = out + (size_t)3 * B;

    int blocks = (B + TPB - 1) / TPB;
    wlog_kernel<<<blocks, TPB>>>(miu1, miu2, cov1, cov2, out_miu, out_cov, B);
}